// round 1
// baseline (speedup 1.0000x reference)
#include <cuda_runtime.h>
#include <cstdint>

// Problem constants
#define BATCH 16384
#define NFEAT 16
#define MTOT  4844      // 16 + 136 + 816 + 3876
#define KPAD  4864      // padded to multiple of 32 (pad monomial=1, pad W=0)
#define OUTD  256
#define BM    16        // batch rows per CTA
#define KC    32        // K chunk
#define NTHR  128

typedef unsigned long long ull;

// Static device scratch (no cudaMalloc allowed)
__device__ float    g_Wt[KPAD * OUTD];   // transposed weights [K][256], ~5MB
__device__ uint32_t g_TBL[KPAD];         // per-monomial: e1 | (e2<<16) into E-table
__device__ uint32_t g_PAIRT[136];        // pair rank -> (i | j<<8)

__device__ __forceinline__ int pair_rank(int a, int b) {
    // lex rank of pair (a<=b) over 16 vars
    return a * 16 - (a * (a - 1)) / 2 + (b - a);
}

// Build monomial tables. The reference expansion enumerates, per degree block,
// the sorted tuples in lexicographic order:
//   deg1: [0,16)      (i)
//   deg2: [16,152)    (a,b) a<=b lex
//   deg3: [152,968)   (a,b,c) lex
//   deg4: [968,4844)  (a,b,c,d) lex
// Each monomial value = E[e1]*E[e2], where per-row E = {1, t_0..t_15, t_i*t_j}.
__global__ void init_tables() {
    int m = blockIdx.x * blockDim.x + threadIdx.x;
    if (m < 136) {
        int r = m, a = 0;
        while (r >= 16 - a) { r -= 16 - a; a++; }
        int b = a + r;
        g_PAIRT[m] = (uint32_t)a | ((uint32_t)b << 8);
    }
    if (m < KPAD) {
        uint32_t e1 = 0, e2 = 0;
        if (m < 16) {
            e1 = 1 + m; e2 = 0;                    // t_m * 1
        } else if (m < 152) {
            e1 = 17 + (m - 16); e2 = 0;            // pair * 1
        } else if (m < 968) {
            int r = m - 152;
            int a = 0;
            while (true) { int k = 16 - a; int t2 = k * (k + 1) / 2; if (r < t2) break; r -= t2; a++; }
            int b = a;
            while (r >= 16 - b) { r -= 16 - b; b++; }
            int c = b + r;
            e1 = 1 + a; e2 = 17 + pair_rank(b, c); // t_a * pair(b,c)
        } else if (m < MTOT) {
            int r = m - 968;
            int a = 0;
            while (true) { int k = 16 - a; int t3 = k * (k + 1) * (k + 2) / 6; if (r < t3) break; r -= t3; a++; }
            int b = a;
            while (true) { int k = 16 - b; int t2 = k * (k + 1) / 2; if (r < t2) break; r -= t2; b++; }
            int c = b;
            while (r >= 16 - c) { r -= 16 - c; c++; }
            int d = c + r;
            e1 = 17 + pair_rank(a, b); e2 = 17 + pair_rank(c, d); // pair*pair
        } else {
            e1 = 0; e2 = 0;  // pad monomial: 1*1 (weight padded to 0)
        }
        g_TBL[m] = e1 | (e2 << 16);
    }
}

// Transpose W [256, 4844] -> g_Wt [KPAD, 256] (coalesced reads, zero-pad K)
__global__ void transpose_w(const float* __restrict__ W) {
    int r = blockIdx.x;  // 0..255
    for (int m = threadIdx.x; m < KPAD; m += blockDim.x) {
        g_Wt[(size_t)m * OUTD + r] = (m < MTOT) ? W[(size_t)r * MTOT + m] : 0.0f;
    }
}

// Packed fp32x2 FMA (SASS FFMA2 — full-width FP32 datapath)
__device__ __forceinline__ void ffma2(ull& d, ull a, ull b) {
    asm("fma.rn.f32x2 %0, %1, %2, %0;" : "+l"(d) : "l"(a), "l"(b));
}
__device__ __forceinline__ ull pack2(float x) {
    ull d;
    asm("mov.b64 %0, {%1, %1};" : "=l"(d) : "f"(x));
    return d;
}

// Main fused kernel: per CTA = 16 batch rows x all 256 output cols.
// 128 threads; thread t owns cols t and t+128, accumulating all 16 rows
// (as 8 packed f32x2 accumulators per col).
__global__ void __launch_bounds__(NTHR, 5) taylor_main(
    const float* __restrict__ x,
    const float* __restrict__ bias,
    float* __restrict__ out)
{
    __shared__ float sE[BM * 161];                      // per-row entry table (pad 161 -> conflict-free)
    __shared__ __align__(16) float sEpd[KC * BM];       // monomial chunk [kk][row]

    const int tid = threadIdx.x;
    const int b0  = blockIdx.x * BM;
    const int c0  = tid;
    const int c1  = tid + 128;

    // ---- Prologue: tanh + pairwise products ----
    #pragma unroll
    for (int i = 0; i < 2; ++i) {                       // 16 rows x 16 feats
        int q   = tid + i * 128;
        int row = q >> 4, f = q & 15;
        float v = x[(size_t)(b0 + row) * NFEAT + f];
        sE[row * 161 + 1 + f] = tanhf(v);
    }
    if (tid < BM) sE[tid * 161] = 1.0f;
    __syncthreads();
    #pragma unroll
    for (int i = 0; i < 17; ++i) {                      // 136 pairs x 16 rows
        int q   = tid + i * 128;
        int row = q & 15, p = q >> 4;
        uint32_t pr = g_PAIRT[p];
        int ia = pr & 255, ib = (pr >> 8) & 255;
        sE[row * 161 + 17 + p] = sE[row * 161 + 1 + ia] * sE[row * 161 + 1 + ib];
    }

    ull acc0[8], acc1[8];
    #pragma unroll
    for (int j = 0; j < 8; ++j) { acc0[j] = 0ull; acc1[j] = 0ull; }

    // ---- Main loop over K in chunks of 32 ----
    for (int k = 0; k < KPAD; k += KC) {
        __syncthreads();   // previous accumulate done reading sEpd (and prologue done for k=0)
        // generate monomial chunk: 32 kk x 16 rows = 512 items, 4/thread
        #pragma unroll
        for (int i = 0; i < 4; ++i) {
            int q   = tid + i * 128;
            int kk  = q >> 4, row = q & 15;
            uint32_t tb = __ldg(&g_TBL[k + kk]);
            sEpd[kk * BM + row] =
                sE[row * 161 + (tb & 0xffff)] * sE[row * 161 + (tb >> 16)];
        }
        __syncthreads();

        const float* wp = g_Wt + (size_t)k * OUTD;
        #pragma unroll
        for (int sub = 0; sub < 4; ++sub) {
            // prefetch 8 kk worth of weights for both columns
            float w0v[8], w1v[8];
            #pragma unroll
            for (int j = 0; j < 8; ++j) {
                int kk = sub * 8 + j;
                w0v[j] = __ldg(&wp[kk * OUTD + c0]);
                w1v[j] = __ldg(&wp[kk * OUTD + c1]);
            }
            #pragma unroll
            for (int j = 0; j < 8; ++j) {
                int kk = sub * 8 + j;
                ull w0 = pack2(w0v[j]);
                ull w1 = pack2(w1v[j]);
                const ulonglong2* ep = (const ulonglong2*)(sEpd + kk * BM);
                #pragma unroll
                for (int t2 = 0; t2 < 4; ++t2) {
                    ulonglong2 e = ep[t2];                 // rows 4*t2 .. 4*t2+3
                    ffma2(acc0[t2 * 2    ], e.x, w0);
                    ffma2(acc0[t2 * 2 + 1], e.y, w0);
                    ffma2(acc1[t2 * 2    ], e.x, w1);
                    ffma2(acc1[t2 * 2 + 1], e.y, w1);
                }
            }
        }
    }

    // ---- Epilogue: bias + relu + store ----
    float bb0 = bias[c0], bb1 = bias[c1];
    #pragma unroll
    for (int j = 0; j < 8; ++j) {
        float2 a0 = *(float2*)&acc0[j];
        float2 a1 = *(float2*)&acc1[j];
        size_t r0 = (size_t)(b0 + 2 * j) * OUTD;
        size_t r1 = r0 + OUTD;
        out[r0 + c0] = fmaxf(a0.x + bb0, 0.0f);
        out[r1 + c0] = fmaxf(a0.y + bb0, 0.0f);
        out[r0 + c1] = fmaxf(a1.x + bb1, 0.0f);
        out[r1 + c1] = fmaxf(a1.y + bb1, 0.0f);
    }
}

extern "C" void kernel_launch(void* const* d_in, const int* in_sizes, int n_in,
                              void* d_out, int out_size) {
    const float* x = (const float*)d_in[0];   // [16384, 16, 1]
    const float* W = (const float*)d_in[1];   // [256, 4844]
    const float* b = (const float*)d_in[2];   // [256, 1]
    float* out = (float*)d_out;               // [16384, 256, 1]

    init_tables<<<(KPAD + 127) / 128, 128>>>();
    transpose_w<<<OUTD, 256>>>(W);
    taylor_main<<<BATCH / BM, NTHR>>>(x, b, out);
}

// round 3
// speedup vs baseline: 4.4848x; 4.4848x over previous
#include <cuda_runtime.h>
#include <cuda_fp16.h>
#include <cstdint>

// ---------------- problem constants ----------------
#define BATCH  16384
#define NFEAT  16
#define MTOT   4844
#define KPAD   4864          // padded K (mult of 64); pad monomial = 1, pad W = 0
#define KSTAGE 64
#define NSTAGE 76            // KPAD / KSTAGE
#define OUTD   256
#define BM     128           // batch rows per CTA
#define NTHR   512
#define ESTRIDE 157          // E-table row stride in floats (conflict-free)

// SMEM layout (dynamic, bytes)
#define A_BUFSZ 18432        // 128 rows x 144B (64 halves + 8 pad)
#define B_BUFSZ 36864        // 256 rows x 144B
#define A_OFF   0
#define B_OFF   (2 * A_BUFSZ)                 // 36864
#define E_OFF   (B_OFF + 2 * B_BUFSZ)         // 110592
#define BIAS_OFF (E_OFF + BM * ESTRIDE * 4)   // 190976
#define SMEM_REQ (BIAS_OFF + OUTD * 4)        // 192000
#define ROWB    144

// ---------------- device globals (no cudaMalloc allowed) ----------------
__device__ __align__(16) __half g_Wh[OUTD * KPAD];  // fp16 W, [N=256][KPAD] K-contiguous
__device__ uint32_t g_TBL[KPAD];     // monomial m -> e1 | (e2<<16) into E table
__device__ uint32_t g_PAIRT[136];    // pair rank -> a | (b<<8)

__device__ __forceinline__ int pair_rank(int a, int b) {
    return a * 16 - (a * (a - 1)) / 2 + (b - a);
}

// Monomial unranking (validated in round 1: rel_err 1.4e-6 with exact fp32).
__global__ void init_tables() {
    int m = blockIdx.x * blockDim.x + threadIdx.x;
    if (m < 136) {
        int r = m, a = 0;
        while (r >= 16 - a) { r -= 16 - a; a++; }
        g_PAIRT[m] = (uint32_t)a | ((uint32_t)(a + r) << 8);
    }
    if (m < KPAD) {
        uint32_t e1 = 0, e2 = 0;
        if (m < 16) {
            e1 = 1 + m; e2 = 0;
        } else if (m < 152) {
            e1 = 17 + (m - 16); e2 = 0;
        } else if (m < 968) {
            int r = m - 152, a = 0;
            while (true) { int k = 16 - a; int t2 = k * (k + 1) / 2; if (r < t2) break; r -= t2; a++; }
            int b = a;
            while (r >= 16 - b) { r -= 16 - b; b++; }
            int c = b + r;
            e1 = 1 + a; e2 = 17 + pair_rank(b, c);
        } else if (m < MTOT) {
            int r = m - 968, a = 0;
            while (true) { int k = 16 - a; int t3 = k * (k + 1) * (k + 2) / 6; if (r < t3) break; r -= t3; a++; }
            int b = a;
            while (true) { int k = 16 - b; int t2 = k * (k + 1) / 2; if (r < t2) break; r -= t2; b++; }
            int c = b;
            while (r >= 16 - c) { r -= 16 - c; c++; }
            int d = c + r;
            e1 = 17 + pair_rank(a, b); e2 = 17 + pair_rank(c, d);
        } else {
            e1 = 0; e2 = 0;   // pad: monomial 1*1, weight forced to 0
        }
        g_TBL[m] = e1 | (e2 << 16);
    }
}

// W [256, 4844] fp32 -> g_Wh [256][KPAD] fp16 (zero pad)
__global__ void prep_w(const float* __restrict__ W) {
    int idx = blockIdx.x * blockDim.x + threadIdx.x;
    if (idx >= OUTD * KPAD) return;
    int n = idx / KPAD, k = idx - n * KPAD;
    float w = (k < MTOT) ? W[(size_t)n * MTOT + k] : 0.0f;
    g_Wh[idx] = __float2half_rn(w);
}

// ---------------- PTX helpers (sm_80-level only; no 'a' features) ----------------
__device__ __forceinline__ uint32_t smem_u32(const void* p) {
    uint32_t a;
    asm("{ .reg .u64 t; cvta.to.shared.u64 t, %1; cvt.u32.u64 %0, t; }" : "=r"(a) : "l"(p));
    return a;
}
__device__ __forceinline__ void cp_async16(uint32_t dst, const void* src) {
    asm volatile("cp.async.cg.shared.global [%0], [%1], 16;" :: "r"(dst), "l"(src) : "memory");
}
__device__ __forceinline__ void cp_commit() {
    asm volatile("cp.async.commit_group;" ::: "memory");
}
__device__ __forceinline__ void ldsm_x4(uint32_t (&r)[4], uint32_t addr) {
    asm volatile("ldmatrix.sync.aligned.m8n8.x4.shared.b16 {%0,%1,%2,%3}, [%4];"
                 : "=r"(r[0]), "=r"(r[1]), "=r"(r[2]), "=r"(r[3]) : "r"(addr));
}
__device__ __forceinline__ void mma16816(float (&c)[4], const uint32_t (&a)[4],
                                         uint32_t b0, uint32_t b1) {
    asm volatile(
        "mma.sync.aligned.m16n8k16.row.col.f32.f16.f16.f32 "
        "{%0,%1,%2,%3}, {%4,%5,%6,%7}, {%8,%9}, {%0,%1,%2,%3};"
        : "+f"(c[0]), "+f"(c[1]), "+f"(c[2]), "+f"(c[3])
        : "r"(a[0]), "r"(a[1]), "r"(a[2]), "r"(a[3]), "r"(b0), "r"(b1));
}

// ---------------- main fused kernel ----------------
// 128 CTAs x 512 threads. CTA tile: M=128 batch rows x N=256 out cols, K staged by 64.
// 16 warps laid out 4x4: warp (wm, wn) computes rows wm*32..+32, cols wn*64..+64.
// A tile (epd, fp16) generated in SMEM from the E table; B tile (W fp16) via cp.async.
__global__ void __launch_bounds__(NTHR, 1) taylor_main(
    const float* __restrict__ x,
    const float* __restrict__ bias,
    float* __restrict__ out)
{
    extern __shared__ char smem[];
    const uint32_t sbase = smem_u32(smem);
    float* E    = (float*)(smem + E_OFF);
    float* Bias = (float*)(smem + BIAS_OFF);

    const int tid  = threadIdx.x;
    const int wid  = tid >> 5;
    const int lane = tid & 31;
    const int b0   = blockIdx.x * BM;
    const int wm   = wid & 3;   // M block (32 rows)
    const int wn   = wid >> 2;  // N block (64 cols)

    // ---- prologue: tanh + pairwise products into E ----
    #pragma unroll
    for (int i = 0; i < (BM * NFEAT) / NTHR; ++i) {
        int q = tid + i * NTHR;
        int row = q >> 4, f = q & 15;
        E[row * ESTRIDE + 1 + f] = tanhf(x[(size_t)(b0 + row) * NFEAT + f]);
    }
    if (tid < BM)   E[tid * ESTRIDE] = 1.0f;
    if (tid < OUTD) Bias[tid] = bias[tid];
    __syncthreads();
    #pragma unroll
    for (int i = 0; i < (136 * BM) / NTHR; ++i) {
        int q = tid + i * NTHR;
        int row = q & 127, p = q >> 7;           // 34 iters: p covers 0..135
        if (p < 136) {
            uint32_t pr = g_PAIRT[p];
            E[row * ESTRIDE + 17 + p] =
                E[row * ESTRIDE + 1 + (pr & 255)] * E[row * ESTRIDE + 1 + ((pr >> 8) & 255)];
        }
    }
    __syncthreads();

    // per-thread gen assignment: row = tid & 127, k-quarter = tid >> 7
    const int grow = tid & 127;
    const int gkb  = (tid >> 7) << 4;            // 0,16,32,48
    const float* Er = E + grow * ESTRIDE;
    const uint32_t gAaddr = sbase + A_OFF + grow * ROWB + gkb * 2;

    // cp.async assignment: 4 chunks of 16B per thread per stage
    // chunk c: row = c>>3 (0..255), seg = c&7
    const uint32_t gBaddr = sbase + B_OFF;

    // generator lambda-ish macros
    #define GEN_A(s_, buf_) do {                                                   \
        const int mb = (s_) * KSTAGE + gkb;                                        \
        uint32_t h[8];                                                             \
        _Pragma("unroll")                                                          \
        for (int q = 0; q < 8; ++q) {                                              \
            uint32_t t0 = __ldg(&g_TBL[mb + 2 * q]);                               \
            uint32_t t1 = __ldg(&g_TBL[mb + 2 * q + 1]);                           \
            float v0 = Er[t0 & 0xffff] * Er[t0 >> 16];                             \
            float v1 = Er[t1 & 0xffff] * Er[t1 >> 16];                             \
            asm("cvt.rn.f16x2.f32 %0, %1, %2;" : "=r"(h[q]) : "f"(v1), "f"(v0));   \
        }                                                                          \
        uint32_t ad = gAaddr + (buf_) * A_BUFSZ;                                   \
        asm volatile("st.shared.v4.b32 [%0], {%1,%2,%3,%4};"                       \
                     :: "r"(ad), "r"(h[0]), "r"(h[1]), "r"(h[2]), "r"(h[3]) : "memory"); \
        asm volatile("st.shared.v4.b32 [%0], {%1,%2,%3,%4};"                       \
                     :: "r"(ad + 16), "r"(h[4]), "r"(h[5]), "r"(h[6]), "r"(h[7]) : "memory"); \
    } while (0)

    #define LOAD_B(s_, buf_) do {                                                  \
        _Pragma("unroll")                                                          \
        for (int i = 0; i < 4; ++i) {                                              \
            int c = tid + i * NTHR;                                                \
            int row = c >> 3, seg = c & 7;                                         \
            const __half* src = g_Wh + (size_t)row * KPAD + (s_) * KSTAGE + seg * 8; \
            cp_async16(gBaddr + (buf_) * B_BUFSZ + row * ROWB + seg * 16, src);    \
        }                                                                          \
        cp_commit();                                                               \
    } while (0)

    // ---- prefetch stages 0 and 1 ----
    GEN_A(0, 0); LOAD_B(0, 0);
    GEN_A(1, 1); LOAD_B(1, 1);

    // accumulators: [mf 2][nf 8][4]
    float acc[2][8][4];
    #pragma unroll
    for (int i = 0; i < 2; ++i)
        #pragma unroll
        for (int j = 0; j < 8; ++j)
            #pragma unroll
            for (int q = 0; q < 4; ++q) acc[i][j][q] = 0.0f;

    // precomputed ldmatrix lane addressing
    const uint32_t aRowAddr = sbase + A_OFF + (wm * 32 + (lane & 15)) * ROWB + (lane >> 4) * 16;
    const int bq = lane >> 3;
    const uint32_t bRowAddr = sbase + B_OFF + (wn * 64 + ((bq >> 1) << 3) + (lane & 7)) * ROWB + (bq & 1) * 16;

    // ---- main loop ----
    for (int s = 0; s < NSTAGE; ++s) {
        const int buf = s & 1;

        if (s == NSTAGE - 1)
            asm volatile("cp.async.wait_group 0;" ::: "memory");
        else
            asm volatile("cp.async.wait_group 1;" ::: "memory");
        __syncthreads();   // B(s) + A(s) visible to all warps

        // compute stage s
        #pragma unroll
        for (int kf = 0; kf < 4; ++kf) {
            uint32_t a[2][4];
            ldsm_x4(a[0], aRowAddr + buf * A_BUFSZ + kf * 32);
            ldsm_x4(a[1], aRowAddr + buf * A_BUFSZ + kf * 32 + 16 * ROWB);
            #pragma unroll
            for (int nb = 0; nb < 4; ++nb) {
                uint32_t b[4];
                ldsm_x4(b, bRowAddr + buf * B_BUFSZ + nb * 16 * ROWB + kf * 32);
                mma16816(acc[0][nb * 2 + 0], a[0], b[0], b[1]);
                mma16816(acc[0][nb * 2 + 1], a[0], b[2], b[3]);
                mma16816(acc[1][nb * 2 + 0], a[1], b[0], b[1]);
                mma16816(acc[1][nb * 2 + 1], a[1], b[2], b[3]);
            }
        }
        __syncthreads();   // all warps done reading buf

        if (s + 2 < NSTAGE) {
            GEN_A(s + 2, buf);
            LOAD_B(s + 2, buf);
        }
    }

    // ---- epilogue: bias + relu + store ----
    {
        const int rbase = b0 + wm * 32 + (lane >> 2);
        const int cbase = wn * 64 + (lane & 3) * 2;
        #pragma unroll
        for (int mf = 0; mf < 2; ++mf) {
            #pragma unroll
            for (int nf = 0; nf < 8; ++nf) {
                const int col = cbase + nf * 8;
                const float bz0 = Bias[col], bz1 = Bias[col + 1];
                const int r0 = rbase + mf * 16;
                float2 v0, v1;
                v0.x = fmaxf(acc[mf][nf][0] + bz0, 0.0f);
                v0.y = fmaxf(acc[mf][nf][1] + bz1, 0.0f);
                v1.x = fmaxf(acc[mf][nf][2] + bz0, 0.0f);
                v1.y = fmaxf(acc[mf][nf][3] + bz1, 0.0f);
                *reinterpret_cast<float2*>(out + (size_t)r0 * OUTD + col)       = v0;
                *reinterpret_cast<float2*>(out + (size_t)(r0 + 8) * OUTD + col) = v1;
            }
        }
    }
    #undef GEN_A
    #undef LOAD_B
}

// ---------------- launch ----------------
extern "C" void kernel_launch(void* const* d_in, const int* in_sizes, int n_in,
                              void* d_out, int out_size) {
    const float* x = (const float*)d_in[0];   // [16384, 16, 1]
    const float* W = (const float*)d_in[1];   // [256, 4844]
    const float* b = (const float*)d_in[2];   // [256, 1]
    float* out = (float*)d_out;               // [16384, 256, 1]

    cudaFuncSetAttribute(taylor_main, cudaFuncAttributeMaxDynamicSharedMemorySize, SMEM_REQ);

    init_tables<<<(KPAD + 127) / 128, 128>>>();
    prep_w<<<(OUTD * KPAD + 255) / 256, 256>>>(W);
    taylor_main<<<BATCH / BM, NTHR, SMEM_REQ>>>(x, b, out);
}